// round 14
// baseline (speedup 1.0000x reference)
#include <cuda_runtime.h>
#include <cuda_fp16.h>
#include <stdint.h>
#include <math.h>

#define BATCH 32
#define SEQ   2048
#define DIM   1024
#define UNITS 1024

// ---------------------------------------------------------------------------
// Scratch (no device allocs allowed)
// ---------------------------------------------------------------------------
#define NSPLIT  32      // S-splits for context
#define NPARTS  8       // N-splits for score
__device__ __half g_values_h[BATCH * SEQ * DIM];   // fp16 copy of values (128MB)
__device__ __half g_W1T_h[UNITS * DIM];            // W1 transposed, fp16 [u][d]
__device__ float  g_qb[BATCH * UNITS];             // query@W2 + b2 + b1
__device__ float  g_scores_part[NPARTS][BATCH * SEQ];
__device__ float  g_ctx_part[NSPLIT][BATCH * DIM];
__device__ int    g_ctr[BATCH];                    // ctx completion counters

// ---------------------------------------------------------------------------
// PTX helpers
// ---------------------------------------------------------------------------
__device__ __forceinline__ uint32_t smem_u32(const void* p) {
    uint32_t a;
    asm("{ .reg .u64 t; cvta.to.shared.u64 t, %1; cvt.u32.u64 %0, t; }" : "=r"(a) : "l"(p));
    return a;
}
#define CP_ASYNC16(s, g) \
    asm volatile("cp.async.cg.shared.global [%0], [%1], 16;" :: "r"(s), "l"(g))
#define CP_COMMIT() asm volatile("cp.async.commit_group;" ::: "memory")
#define CP_WAIT1()  asm volatile("cp.async.wait_group 1;" ::: "memory")
#define CP_WAIT0()  asm volatile("cp.async.wait_group 0;" ::: "memory")

// mma.sync m16n8k16 fp16 inputs, fp32 accum (baseline PTX, sm_80+)
__device__ __forceinline__ void mma_f16(float* d, const uint32_t* a, const uint32_t* b) {
    asm volatile(
        "mma.sync.aligned.m16n8k16.row.col.f32.f16.f16.f32 "
        "{%0,%1,%2,%3}, {%4,%5,%6,%7}, {%8,%9}, {%0,%1,%2,%3};"
        : "+f"(d[0]), "+f"(d[1]), "+f"(d[2]), "+f"(d[3])
        : "r"(a[0]), "r"(a[1]), "r"(a[2]), "r"(a[3]), "r"(b[0]), "r"(b[1]));
}

// ldmatrix x4 (baseline PTX, sm_75+)
__device__ __forceinline__ void ldsm_x4(uint32_t* r, uint32_t saddr) {
    asm volatile("ldmatrix.sync.aligned.m8n8.x4.shared.b16 {%0,%1,%2,%3}, [%4];"
        : "=r"(r[0]), "=r"(r[1]), "=r"(r[2]), "=r"(r[3]) : "r"(saddr));
}

// ---------------------------------------------------------------------------
// FMA-only tanh (no MUFU): abs err < ~5e-5
// ---------------------------------------------------------------------------
__device__ __forceinline__ float tanh_fast(float x) {
    float ax = fminf(fabsf(x), 10.0f);
    float t  = ax * 2.885390081777927f;
    float fn = t + 12582912.0f;
    int   n  = __float_as_int(fn) - __float_as_int(12582912.0f);
    float f  = t - (fn - 12582912.0f);
    float p  = 9.6181e-3f;
    p = fmaf(p, f, 5.5504e-2f);
    p = fmaf(p, f, 2.4022651e-1f);
    p = fmaf(p, f, 6.9314718e-1f);
    p = fmaf(p, f, 1.0f);
    float e = __int_as_float(__float_as_int(p) + (n << 23));
    float d = e + 1.0f;
    float r = __int_as_float(0x7EF311C3u - __float_as_int(d));
    r = r * fmaf(-d, r, 2.0f);
    r = r * fmaf(-d, r, 2.0f);
    float th = fmaf(-2.0f, r, 1.0f);
    return __int_as_float(__float_as_int(th) | (__float_as_int(x) & 0x80000000));
}

// ---------------------------------------------------------------------------
// Fused prep kernel: heterogeneous blocks, all three jobs run concurrently.
// Also resets the ctx completion counters (graph-replay safe: runs first).
// ---------------------------------------------------------------------------
#define PREP_QPROJ_BLKS  BATCH
#define PREP_TRANS_BLKS  ((DIM / 32) * (UNITS / 32))            // 1024
#define PREP_CONV_BLKS   ((BATCH * SEQ * DIM) / (256 * 8))      // 32768
#define PREP_GRID        (PREP_QPROJ_BLKS + PREP_TRANS_BLKS + PREP_CONV_BLKS)

__global__ __launch_bounds__(256) void prep_kernel(
    const float* __restrict__ query, const float* __restrict__ values,
    const float* __restrict__ W1,   const float* __restrict__ b1,
    const float* __restrict__ W2,   const float* __restrict__ b2)
{
    const int tid = threadIdx.x;
    const int bid = blockIdx.x;

    if (bid < PREP_QPROJ_BLKS) {
        if (tid == 0) g_ctr[bid] = 0;            // reset ctx counter
        __shared__ float qrow[DIM];
        const int b = bid;
        for (int i = tid; i < DIM; i += 256)
            qrow[i] = query[b * DIM + i];
        __syncthreads();
        for (int u = tid; u < UNITS; u += 256) {
            float acc = 0.f;
            #pragma unroll 8
            for (int d = 0; d < DIM; d++)
                acc = fmaf(qrow[d], W2[d * UNITS + u], acc);
            g_qb[b * UNITS + u] = acc + b1[u] + b2[u];
        }
    } else if (bid < PREP_QPROJ_BLKS + PREP_TRANS_BLKS) {
        __shared__ float t[32][33];
        const int tile = bid - PREP_QPROJ_BLKS;
        const int d0 = (tile & 31) * 32;
        const int u0 = (tile >> 5) * 32;
        const int tx = tid & 31;
        const int ty = tid >> 5;
        #pragma unroll
        for (int i = 0; i < 4; i++) {
            int r = ty + i * 8;
            t[r][tx] = W1[(size_t)(d0 + r) * UNITS + u0 + tx];
        }
        __syncthreads();
        #pragma unroll
        for (int i = 0; i < 4; i++) {
            int r = ty + i * 8;
            g_W1T_h[(size_t)(u0 + r) * DIM + d0 + tx] = __float2half_rn(t[tx][r]);
        }
    } else {
        const size_t idx = (size_t)(bid - PREP_QPROJ_BLKS - PREP_TRANS_BLKS) * 256 + tid;
        const float4* in = (const float4*)values;
        float4 v0 = in[idx * 2];
        float4 v1 = in[idx * 2 + 1];
        __half2 h0 = __floats2half2_rn(v0.x, v0.y);
        __half2 h1 = __floats2half2_rn(v0.z, v0.w);
        __half2 h2 = __floats2half2_rn(v1.x, v1.y);
        __half2 h3 = __floats2half2_rn(v1.z, v1.w);
        uint4 o;
        o.x = *(uint32_t*)&h0; o.y = *(uint32_t*)&h1;
        o.z = *(uint32_t*)&h2; o.w = *(uint32_t*)&h3;
        ((uint4*)g_values_h)[idx] = o;
    }
}

// ---------------------------------------------------------------------------
// Kernel 2: fused score GEMM via mma.sync fp16 (m16n8k16) + ldmatrix
// CTA tile 128(M) x 128(N) (one N-eighth), K chunks of 64 -> 16 chunks.
// Grid = 4096. 2 CTAs/SM (smem 111KB x2 = 222KB <= 228KB, regs <= 128).
// 3-stage cp.async pipeline with wait_group 1 (one chunk always in flight).
// 256 threads = 8 warps (2M x 4N), warp tile 64x32.
// ---------------------------------------------------------------------------
#define KC        64
#define A_PITCH_H 72                   // 144 B rows: conflict-free LDSM + cp.async
#define B_PITCH_H 72
#define A_STAGE_H (128 * A_PITCH_H)    // 9216 halfs
#define B_STAGE_H (128 * B_PITCH_H)    // 9216 halfs
#define OFF_B_H   (3 * A_STAGE_H)      // 27648 halfs
#define SMEM_HALFS (OFF_B_H + 3 * B_STAGE_H)         // 55296 halfs
#define OFF_SC_BYTES (SMEM_HALFS * 2)                // 110592
#define SMEM_SCORE_BYTES (OFF_SC_BYTES + 128 * 4)    // 111104

__device__ __forceinline__ void load_chunk(uint32_t sb, int stage, int m0, int n0,
                                           int c, int tid)
{
    const int k0 = c * KC;
    const uint32_t a_s = sb + stage * A_STAGE_H * 2;
    const uint32_t b_s = sb + (OFF_B_H + stage * B_STAGE_H) * 2;
    // A: values_h tile 128 x 64 halfs (1024 16B chunks / 256 thr = 4)
    #pragma unroll
    for (int t = 0; t < 4; t++) {
        int idx = tid + t * 256;
        int r = idx >> 3, cc = idx & 7;
        CP_ASYNC16(a_s + r * 144 + cc * 16,
                   g_values_h + (size_t)(m0 + r) * DIM + k0 + cc * 8);
    }
    // B: W1T_h tile 128 x 64 halfs (1024 chunks / 256 thr = 4)
    #pragma unroll
    for (int t = 0; t < 4; t++) {
        int idx = tid + t * 256;
        int r = idx >> 3, cc = idx & 7;
        CP_ASYNC16(b_s + r * 144 + cc * 16,
                   g_W1T_h + (size_t)(n0 + r) * DIM + k0 + cc * 8);
    }
}

__global__ __launch_bounds__(256, 2) void score_kernel(const float* __restrict__ V)
{
    extern __shared__ __align__(16) char smraw[];
    float* s_sc = (float*)(smraw + OFF_SC_BYTES);
    const uint32_t sb = smem_u32(smraw);

    const int tid  = threadIdx.x;
    const int warp = tid >> 5;
    const int lane = tid & 31;
    const int wm   = warp >> 2;          // 0..1 (M)
    const int wn   = warp & 3;           // 0..3 (N)
    const int grp  = lane >> 2;          // 0..7
    const int ctg  = lane & 3;           // 0..3
    const int npart = blockIdx.x & 7;                // 0..7
    const int m0    = (blockIdx.x >> 3) * 128;
    const int nbase = npart * 128;
    const int b     = m0 >> 11;

    const int lrow = ((lane >> 3) & 1) * 8 + (lane & 7);   // 0..15
    const int lkoc = ((lane >> 4) & 1) * 8;                // 0 or 8

    if (tid < 128) s_sc[tid] = 0.f;

    float acc[4][4][4];
    #pragma unroll
    for (int mi = 0; mi < 4; mi++)
        #pragma unroll
        for (int ni = 0; ni < 4; ni++)
            #pragma unroll
            for (int r = 0; r < 4; r++)
                acc[mi][ni][r] = 0.f;

    load_chunk(sb, 0, m0, nbase, 0, tid); CP_COMMIT();
    load_chunk(sb, 1, m0, nbase, 1, tid); CP_COMMIT();

    for (int c = 0; c < 16; c++) {
        const int stage = c % 3;
        if (c + 2 < 16) {
            CP_WAIT1();                  // chunk c done; c+1 still in flight
            __syncthreads();
            load_chunk(sb, (c + 2) % 3, m0, nbase, c + 2, tid);
            CP_COMMIT();
        } else if (c + 1 < 16) {
            CP_WAIT1();
            __syncthreads();
        } else {
            CP_WAIT0();
            __syncthreads();
        }

        const uint32_t a_base = sb + stage * A_STAGE_H * 2
                              + ((wm * 64 + lrow) * A_PITCH_H + lkoc) * 2;
        const uint32_t b_base = sb + (OFF_B_H + stage * B_STAGE_H) * 2
                              + ((wn * 32 + lrow) * B_PITCH_H + lkoc) * 2;

        #pragma unroll
        for (int k16 = 0; k16 < KC / 16; k16++) {
            const int kb = k16 * 16;
            uint32_t afr[4][4], bfr[4][2];
            #pragma unroll
            for (int mi = 0; mi < 4; mi++)
                ldsm_x4(afr[mi], a_base + (mi * 16 * A_PITCH_H + kb) * 2);
            #pragma unroll
            for (int pr = 0; pr < 2; pr++) {
                uint32_t tmp[4];
                ldsm_x4(tmp, b_base + (pr * 16 * B_PITCH_H + kb) * 2);
                bfr[2 * pr][0]     = tmp[0];
                bfr[2 * pr + 1][0] = tmp[1];
                bfr[2 * pr][1]     = tmp[2];
                bfr[2 * pr + 1][1] = tmp[3];
            }
            #pragma unroll
            for (int mi = 0; mi < 4; mi++)
                #pragma unroll
                for (int ni = 0; ni < 4; ni++)
                    mma_f16(acc[mi][ni], afr[mi], bfr[ni]);
        }
        __syncthreads();
    }

    // epilogue: tanh(acc + qb) * V for this CTA's N-eighth
    float p[4][2];
    #pragma unroll
    for (int i = 0; i < 4; i++) { p[i][0] = 0.f; p[i][1] = 0.f; }
    #pragma unroll
    for (int ni = 0; ni < 4; ni++) {
        const int nloc = nbase + wn * 32 + ni * 8 + ctg * 2;
        const float2 q2 = *(const float2*)&g_qb[b * UNITS + nloc];
        const float2 v2 = *(const float2*)&V[nloc];
        #pragma unroll
        for (int mi = 0; mi < 4; mi++) {
            p[mi][0] = fmaf(tanh_fast(acc[mi][ni][0] + q2.x), v2.x, p[mi][0]);
            p[mi][0] = fmaf(tanh_fast(acc[mi][ni][1] + q2.y), v2.y, p[mi][0]);
            p[mi][1] = fmaf(tanh_fast(acc[mi][ni][2] + q2.x), v2.x, p[mi][1]);
            p[mi][1] = fmaf(tanh_fast(acc[mi][ni][3] + q2.y), v2.y, p[mi][1]);
        }
    }

    // reduce over quad lanes (ctg), then across the 4 n-warps via smem atomics
    #pragma unroll
    for (int mi = 0; mi < 4; mi++) {
        #pragma unroll
        for (int r = 0; r < 2; r++) {
            float v = p[mi][r];
            v += __shfl_xor_sync(0xffffffffu, v, 1);
            v += __shfl_xor_sync(0xffffffffu, v, 2);
            if (ctg == 0)
                atomicAdd(&s_sc[wm * 64 + mi * 16 + r * 8 + grp], v);
        }
    }
    __syncthreads();
    if (tid < 128) g_scores_part[npart][m0 + tid] = s_sc[tid];
}

// ---------------------------------------------------------------------------
// Kernel 3: fused softmax + context partial + last-block final reduce.
// Each (b, sp) block recomputes softmax stats from the 8 N-split partials,
// writes its w_out slice, accumulates its S-split of the weighted sum, then
// the LAST finishing block of each batch sums the 32 partials in fixed order
// and writes ctx_out (deterministic: fixed-order sum, single writer).
// ---------------------------------------------------------------------------
#define SPAN (SEQ / NSPLIT)   // 64

__global__ __launch_bounds__(256) void ctx_fused_kernel(
    float* __restrict__ w_out, float* __restrict__ ctx_out)
{
    __shared__ float e_sm[SEQ];      // 8KB
    __shared__ float sred[8];
    __shared__ int   is_last;
    const int b   = blockIdx.x;
    const int sp  = blockIdx.y;
    const int tid = threadIdx.x;

    // ---- softmax stats (sum the 8 N-split partials) ----
    float m = -1e30f;
    for (int i = tid; i < SEQ; i += 256) {
        float s = 0.f;
        #pragma unroll
        for (int q = 0; q < NPARTS; q++) s += g_scores_part[q][b * SEQ + i];
        e_sm[i] = s;                      // stash raw score
        m = fmaxf(m, s);
    }
    #pragma unroll
    for (int off = 16; off > 0; off >>= 1)
        m = fmaxf(m, __shfl_xor_sync(0xffffffffu, m, off));
    if ((tid & 31) == 0) sred[tid >> 5] = m;
    __syncthreads();
    if (tid == 0) {
        float mm = sred[0];
        #pragma unroll
        for (int i = 1; i < 8; i++) mm = fmaxf(mm, sred[i]);
        sred[0] = mm;
    }
    __syncthreads();
    const float bm = sred[0];
    __syncthreads();

    float sum = 0.f;
    for (int i = tid; i < SEQ; i += 256) {
        float e = __expf(e_sm[i] - bm);
        e_sm[i] = e;
        sum += e;
    }
    __syncthreads();    // e_sm writes visible
    #pragma unroll
    for (int off = 16; off > 0; off >>= 1)
        sum += __shfl_xor_sync(0xffffffffu, sum, off);
    if ((tid & 31) == 0) sred[tid >> 5] = sum;
    __syncthreads();
    if (tid == 0) {
        float s = 0.f;
        #pragma unroll
        for (int i = 0; i < 8; i++) s += sred[i];
        sred[0] = s;
    }
    __syncthreads();
    const float inv = 1.f / sred[0];

    const int s0 = sp * SPAN;

    // ---- this split's slice of attention_weights output ----
    if (w_out) {
        for (int i = s0 + tid; i < s0 + SPAN; i += 256)
            w_out[b * SEQ + i] = e_sm[i] * inv;
    }

    // ---- weighted sum over this split's S range (4-way MLP) ----
    const uint2* vp = (const uint2*)(g_values_h + (size_t)b * SEQ * DIM);
    float4 acc = make_float4(0.f, 0.f, 0.f, 0.f);
    #pragma unroll 1
    for (int s = s0; s < s0 + SPAN; s += 4) {
        float w0 = e_sm[s]     * inv;
        float w1 = e_sm[s + 1] * inv;
        float w2 = e_sm[s + 2] * inv;
        float w3 = e_sm[s + 3] * inv;
        uint2 u0 = vp[(size_t)(s)     * 256 + tid];
        uint2 u1 = vp[(size_t)(s + 1) * 256 + tid];
        uint2 u2 = vp[(size_t)(s + 2) * 256 + tid];
        uint2 u3 = vp[(size_t)(s + 3) * 256 + tid];
        float2 a0 = __half22float2(*(const __half2*)&u0.x);
        float2 a1 = __half22float2(*(const __half2*)&u0.y);
        float2 b0 = __half22float2(*(const __half2*)&u1.x);
        float2 b1 = __half22float2(*(const __half2*)&u1.y);
        float2 c0 = __half22float2(*(const __half2*)&u2.x);
        float2 c1 = __half22float2(*(const __half2*)&u2.y);
        float2 d0 = __half22float2(*(const __half2*)&u3.x);
        float2 d1 = __half22float2(*(const __half2*)&u3.y);
        acc.x = fmaf(w0, a0.x, fmaf(w1, b0.x, fmaf(w2, c0.x, fmaf(w3, d0.x, acc.x))));
        acc.y = fmaf(w0, a0.y, fmaf(w1, b0.y, fmaf(w2, c0.y, fmaf(w3, d0.y, acc.y))));
        acc.z = fmaf(w0, a1.x, fmaf(w1, b1.x, fmaf(w2, c1.x, fmaf(w3, d1.x, acc.z))));
        acc.w = fmaf(w0, a1.y, fmaf(w1, b1.y, fmaf(w2, c1.y, fmaf(w3, d1.y, acc.w))));
    }
    ((float4*)&g_ctx_part[sp][b * DIM])[tid] = acc;

    if (!ctx_out) return;

    // ---- last block of this batch performs the final reduce ----
    __threadfence();
    if (tid == 0)
        is_last = (atomicAdd(&g_ctr[b], 1) == NSPLIT - 1);
    __syncthreads();
    if (is_last) {
        float4 r = make_float4(0.f, 0.f, 0.f, 0.f);
        #pragma unroll
        for (int q = 0; q < NSPLIT; q++) {
            float4 v = ((const float4*)&g_ctx_part[q][b * DIM])[tid];
            r.x += v.x; r.y += v.y; r.z += v.z; r.w += v.w;
        }
        ((float4*)&ctx_out[b * DIM])[tid] = r;
    }
}

// ---------------------------------------------------------------------------
// Launch: inputs = query, values, W1, b1, W2, b2, V, bV
// ---------------------------------------------------------------------------
extern "C" void kernel_launch(void* const* d_in, const int* in_sizes, int n_in,
                              void* d_out, int out_size)
{
    const float* query  = (const float*)d_in[0];
    const float* values = (const float*)d_in[1];
    const float* W1     = (const float*)d_in[2];
    const float* b1     = (const float*)d_in[3];
    const float* W2     = (const float*)d_in[4];
    const float* b2     = (const float*)d_in[5];
    const float* V      = (const float*)d_in[6];
    // bV shifts every score equally -> softmax-invariant; unused.

    float* out = (float*)d_out;
    float* ctx_out = nullptr;
    float* w_out   = nullptr;
    if (out_size >= BATCH * DIM + BATCH * SEQ) {
        ctx_out = out;
        w_out   = out + BATCH * DIM;
    } else if (out_size == BATCH * SEQ) {
        w_out = out;
    } else {
        ctx_out = out;
    }

    static int smem_set = 0;
    if (!smem_set) {
        cudaFuncSetAttribute(score_kernel, cudaFuncAttributeMaxDynamicSharedMemorySize,
                             SMEM_SCORE_BYTES);
        smem_set = 1;
    }

    prep_kernel<<<PREP_GRID, 256>>>(query, values, W1, b1, W2, b2);
    score_kernel<<<(BATCH * SEQ) / 128 * NPARTS, 256, SMEM_SCORE_BYTES>>>(V);
    ctx_fused_kernel<<<dim3(BATCH, NSPLIT), 256>>>(w_out, ctx_out);
}

// round 15
// speedup vs baseline: 1.2419x; 1.2419x over previous
#include <cuda_runtime.h>
#include <cuda_fp16.h>
#include <stdint.h>
#include <math.h>

#define BATCH 32
#define SEQ   2048
#define DIM   1024
#define UNITS 1024

// ---------------------------------------------------------------------------
// Scratch (no device allocs allowed)
// ---------------------------------------------------------------------------
#define NSPLIT  32      // S-splits for context
#define NPARTS  8       // N-splits for score
__device__ __half g_values_h[BATCH * SEQ * DIM];   // fp16 copy of values (128MB)
__device__ __half g_W1T_h[UNITS * DIM];            // W1 transposed, fp16 [u][d]
__device__ float  g_qb[BATCH * UNITS];             // query@W2 + b2 + b1
__device__ float  g_scores_part[NPARTS][BATCH * SEQ];
__device__ float  g_ctx_part[NSPLIT][BATCH * DIM];
__device__ int    g_ctr[BATCH];                    // ctx completion counters

// ---------------------------------------------------------------------------
// PTX helpers
// ---------------------------------------------------------------------------
__device__ __forceinline__ uint32_t smem_u32(const void* p) {
    uint32_t a;
    asm("{ .reg .u64 t; cvta.to.shared.u64 t, %1; cvt.u32.u64 %0, t; }" : "=r"(a) : "l"(p));
    return a;
}
#define CP_ASYNC16(s, g) \
    asm volatile("cp.async.cg.shared.global [%0], [%1], 16;" :: "r"(s), "l"(g))
#define CP_COMMIT() asm volatile("cp.async.commit_group;" ::: "memory")
#define CP_WAIT0()  asm volatile("cp.async.wait_group 0;" ::: "memory")

// mma.sync m16n8k16 fp16 inputs, fp32 accum (baseline PTX, sm_80+)
__device__ __forceinline__ void mma_f16(float* d, const uint32_t* a, const uint32_t* b) {
    asm volatile(
        "mma.sync.aligned.m16n8k16.row.col.f32.f16.f16.f32 "
        "{%0,%1,%2,%3}, {%4,%5,%6,%7}, {%8,%9}, {%0,%1,%2,%3};"
        : "+f"(d[0]), "+f"(d[1]), "+f"(d[2]), "+f"(d[3])
        : "r"(a[0]), "r"(a[1]), "r"(a[2]), "r"(a[3]), "r"(b[0]), "r"(b[1]));
}

// ldmatrix x4 (baseline PTX, sm_75+)
__device__ __forceinline__ void ldsm_x4(uint32_t* r, uint32_t saddr) {
    asm volatile("ldmatrix.sync.aligned.m8n8.x4.shared.b16 {%0,%1,%2,%3}, [%4];"
        : "=r"(r[0]), "=r"(r[1]), "=r"(r[2]), "=r"(r[3]) : "r"(saddr));
}

// ---------------------------------------------------------------------------
// FMA-only tanh (no MUFU): abs err < ~5e-5
// ---------------------------------------------------------------------------
__device__ __forceinline__ float tanh_fast(float x) {
    float ax = fminf(fabsf(x), 10.0f);
    float t  = ax * 2.885390081777927f;
    float fn = t + 12582912.0f;
    int   n  = __float_as_int(fn) - __float_as_int(12582912.0f);
    float f  = t - (fn - 12582912.0f);
    float p  = 9.6181e-3f;
    p = fmaf(p, f, 5.5504e-2f);
    p = fmaf(p, f, 2.4022651e-1f);
    p = fmaf(p, f, 6.9314718e-1f);
    p = fmaf(p, f, 1.0f);
    float e = __int_as_float(__float_as_int(p) + (n << 23));
    float d = e + 1.0f;
    float r = __int_as_float(0x7EF311C3u - __float_as_int(d));
    r = r * fmaf(-d, r, 2.0f);
    r = r * fmaf(-d, r, 2.0f);
    float th = fmaf(-2.0f, r, 1.0f);
    return __int_as_float(__float_as_int(th) | (__float_as_int(x) & 0x80000000));
}

// ---------------------------------------------------------------------------
// Fused prep kernel: heterogeneous blocks, all jobs run concurrently.
//   qproj: loop-swapped so W2 is read COALESCED row-by-row (thread t owns
//          u = t, t+256, t+512, t+768); qrow broadcast from smem.
//   convert: 16 floats/thread (4 independent LDG.128 -> 2 STG.128).
// ---------------------------------------------------------------------------
#define PREP_QPROJ_BLKS  BATCH
#define PREP_TRANS_BLKS  ((DIM / 32) * (UNITS / 32))            // 1024
#define PREP_CONV_BLKS   ((BATCH * SEQ * DIM) / (256 * 16))     // 16384
#define PREP_GRID        (PREP_QPROJ_BLKS + PREP_TRANS_BLKS + PREP_CONV_BLKS)

__global__ __launch_bounds__(256) void prep_kernel(
    const float* __restrict__ query, const float* __restrict__ values,
    const float* __restrict__ W1,   const float* __restrict__ b1,
    const float* __restrict__ W2,   const float* __restrict__ b2)
{
    const int tid = threadIdx.x;
    const int bid = blockIdx.x;

    if (bid < PREP_QPROJ_BLKS) {
        if (tid == 0) g_ctr[bid] = 0;            // reset ctx counter
        __shared__ float qrow[DIM];
        const int b = bid;
        for (int i = tid; i < DIM; i += 256)
            qrow[i] = query[b * DIM + i];
        __syncthreads();
        float acc0 = 0.f, acc1 = 0.f, acc2 = 0.f, acc3 = 0.f;
        #pragma unroll 4
        for (int d = 0; d < DIM; d++) {
            const float qd = qrow[d];
            const float* w = W2 + (size_t)d * UNITS;
            acc0 = fmaf(qd, w[tid],       acc0);
            acc1 = fmaf(qd, w[tid + 256], acc1);
            acc2 = fmaf(qd, w[tid + 512], acc2);
            acc3 = fmaf(qd, w[tid + 768], acc3);
        }
        g_qb[b * UNITS + tid]       = acc0 + b1[tid]       + b2[tid];
        g_qb[b * UNITS + tid + 256] = acc1 + b1[tid + 256] + b2[tid + 256];
        g_qb[b * UNITS + tid + 512] = acc2 + b1[tid + 512] + b2[tid + 512];
        g_qb[b * UNITS + tid + 768] = acc3 + b1[tid + 768] + b2[tid + 768];
    } else if (bid < PREP_QPROJ_BLKS + PREP_TRANS_BLKS) {
        __shared__ float t[32][33];
        const int tile = bid - PREP_QPROJ_BLKS;
        const int d0 = (tile & 31) * 32;
        const int u0 = (tile >> 5) * 32;
        const int tx = tid & 31;
        const int ty = tid >> 5;
        #pragma unroll
        for (int i = 0; i < 4; i++) {
            int r = ty + i * 8;
            t[r][tx] = W1[(size_t)(d0 + r) * UNITS + u0 + tx];
        }
        __syncthreads();
        #pragma unroll
        for (int i = 0; i < 4; i++) {
            int r = ty + i * 8;
            g_W1T_h[(size_t)(u0 + r) * DIM + d0 + tx] = __float2half_rn(t[tx][r]);
        }
    } else {
        // convert: 16 floats per thread, 4 independent LDG.128
        const size_t base = ((size_t)(bid - PREP_QPROJ_BLKS - PREP_TRANS_BLKS) * 256 + tid) * 4;
        const float4* in = (const float4*)values;
        float4 v0 = in[base + 0];
        float4 v1 = in[base + 1];
        float4 v2 = in[base + 2];
        float4 v3 = in[base + 3];
        __half2 h0 = __floats2half2_rn(v0.x, v0.y), h1 = __floats2half2_rn(v0.z, v0.w);
        __half2 h2 = __floats2half2_rn(v1.x, v1.y), h3 = __floats2half2_rn(v1.z, v1.w);
        __half2 h4 = __floats2half2_rn(v2.x, v2.y), h5 = __floats2half2_rn(v2.z, v2.w);
        __half2 h6 = __floats2half2_rn(v3.x, v3.y), h7 = __floats2half2_rn(v3.z, v3.w);
        uint4 o0, o1;
        o0.x = *(uint32_t*)&h0; o0.y = *(uint32_t*)&h1;
        o0.z = *(uint32_t*)&h2; o0.w = *(uint32_t*)&h3;
        o1.x = *(uint32_t*)&h4; o1.y = *(uint32_t*)&h5;
        o1.z = *(uint32_t*)&h6; o1.w = *(uint32_t*)&h7;
        ((uint4*)g_values_h)[base / 2]     = o0;
        ((uint4*)g_values_h)[base / 2 + 1] = o1;
    }
}

// ---------------------------------------------------------------------------
// Kernel 2: fused score GEMM via mma.sync fp16 (m16n8k16) + ldmatrix
// CTA tile 128(M) x 128(N) (one N-eighth), K chunks of 64 -> 16 chunks.
// Grid = 4096. 2 CTAs/SM (smem 74KB, regs <= 128): co-resident CTAs
// desynchronize, overlapping LDSM ramps with MMA bursts.
// 256 threads = 8 warps (2M x 4N), warp tile 64x32. 2-stage cp.async.
// ---------------------------------------------------------------------------
#define KC        64
#define A_PITCH_H 72                   // 144 B rows: conflict-free LDSM + cp.async
#define B_PITCH_H 72
#define A_STAGE_H (128 * A_PITCH_H)    // 9216 halfs
#define B_STAGE_H (128 * B_PITCH_H)    // 9216 halfs
#define OFF_B_H   (2 * A_STAGE_H)      // 18432 halfs
#define SMEM_HALFS (OFF_B_H + 2 * B_STAGE_H)         // 36864 halfs
#define OFF_SC_BYTES (SMEM_HALFS * 2)                // 73728
#define SMEM_SCORE_BYTES (OFF_SC_BYTES + 128 * 4)    // 74240

__device__ __forceinline__ void load_chunk(uint32_t sb, int stage, int m0, int n0,
                                           int c, int tid)
{
    const int k0 = c * KC;
    const uint32_t a_s = sb + stage * A_STAGE_H * 2;
    const uint32_t b_s = sb + (OFF_B_H + stage * B_STAGE_H) * 2;
    #pragma unroll
    for (int t = 0; t < 4; t++) {
        int idx = tid + t * 256;
        int r = idx >> 3, cc = idx & 7;
        CP_ASYNC16(a_s + r * 144 + cc * 16,
                   g_values_h + (size_t)(m0 + r) * DIM + k0 + cc * 8);
    }
    #pragma unroll
    for (int t = 0; t < 4; t++) {
        int idx = tid + t * 256;
        int r = idx >> 3, cc = idx & 7;
        CP_ASYNC16(b_s + r * 144 + cc * 16,
                   g_W1T_h + (size_t)(n0 + r) * DIM + k0 + cc * 8);
    }
}

__global__ __launch_bounds__(256, 2) void score_kernel(const float* __restrict__ V)
{
    extern __shared__ __align__(16) char smraw[];
    float* s_sc = (float*)(smraw + OFF_SC_BYTES);
    const uint32_t sb = smem_u32(smraw);

    const int tid  = threadIdx.x;
    const int warp = tid >> 5;
    const int lane = tid & 31;
    const int wm   = warp >> 2;          // 0..1 (M)
    const int wn   = warp & 3;           // 0..3 (N)
    const int grp  = lane >> 2;          // 0..7
    const int ctg  = lane & 3;           // 0..3
    const int npart = blockIdx.x & 7;                // 0..7
    const int m0    = (blockIdx.x >> 3) * 128;
    const int nbase = npart * 128;
    const int b     = m0 >> 11;

    const int lrow = ((lane >> 3) & 1) * 8 + (lane & 7);   // 0..15
    const int lkoc = ((lane >> 4) & 1) * 8;                // 0 or 8

    if (tid < 128) s_sc[tid] = 0.f;

    float acc[4][4][4];
    #pragma unroll
    for (int mi = 0; mi < 4; mi++)
        #pragma unroll
        for (int ni = 0; ni < 4; ni++)
            #pragma unroll
            for (int r = 0; r < 4; r++)
                acc[mi][ni][r] = 0.f;

    load_chunk(sb, 0, m0, nbase, 0, tid); CP_COMMIT();

    for (int c = 0; c < 16; c++) {
        const int stage = c & 1;
        CP_WAIT0();
        __syncthreads();
        if (c + 1 < 16) {
            load_chunk(sb, (c + 1) & 1, m0, nbase, c + 1, tid);
            CP_COMMIT();
        }

        const uint32_t a_base = sb + stage * A_STAGE_H * 2
                              + ((wm * 64 + lrow) * A_PITCH_H + lkoc) * 2;
        const uint32_t b_base = sb + (OFF_B_H + stage * B_STAGE_H) * 2
                              + ((wn * 32 + lrow) * B_PITCH_H + lkoc) * 2;

        #pragma unroll
        for (int k16 = 0; k16 < KC / 16; k16++) {
            const int kb = k16 * 16;
            uint32_t afr[4][4], bfr[4][2];
            #pragma unroll
            for (int mi = 0; mi < 4; mi++)
                ldsm_x4(afr[mi], a_base + (mi * 16 * A_PITCH_H + kb) * 2);
            #pragma unroll
            for (int pr = 0; pr < 2; pr++) {
                uint32_t tmp[4];
                ldsm_x4(tmp, b_base + (pr * 16 * B_PITCH_H + kb) * 2);
                bfr[2 * pr][0]     = tmp[0];
                bfr[2 * pr + 1][0] = tmp[1];
                bfr[2 * pr][1]     = tmp[2];
                bfr[2 * pr + 1][1] = tmp[3];
            }
            #pragma unroll
            for (int mi = 0; mi < 4; mi++)
                #pragma unroll
                for (int ni = 0; ni < 4; ni++)
                    mma_f16(acc[mi][ni], afr[mi], bfr[ni]);
        }
        __syncthreads();
    }

    // epilogue: tanh(acc + qb) * V for this CTA's N-eighth
    float p[4][2];
    #pragma unroll
    for (int i = 0; i < 4; i++) { p[i][0] = 0.f; p[i][1] = 0.f; }
    #pragma unroll
    for (int ni = 0; ni < 4; ni++) {
        const int nloc = nbase + wn * 32 + ni * 8 + ctg * 2;
        const float2 q2 = *(const float2*)&g_qb[b * UNITS + nloc];
        const float2 v2 = *(const float2*)&V[nloc];
        #pragma unroll
        for (int mi = 0; mi < 4; mi++) {
            p[mi][0] = fmaf(tanh_fast(acc[mi][ni][0] + q2.x), v2.x, p[mi][0]);
            p[mi][0] = fmaf(tanh_fast(acc[mi][ni][1] + q2.y), v2.y, p[mi][0]);
            p[mi][1] = fmaf(tanh_fast(acc[mi][ni][2] + q2.x), v2.x, p[mi][1]);
            p[mi][1] = fmaf(tanh_fast(acc[mi][ni][3] + q2.y), v2.y, p[mi][1]);
        }
    }

    #pragma unroll
    for (int mi = 0; mi < 4; mi++) {
        #pragma unroll
        for (int r = 0; r < 2; r++) {
            float v = p[mi][r];
            v += __shfl_xor_sync(0xffffffffu, v, 1);
            v += __shfl_xor_sync(0xffffffffu, v, 2);
            if (ctg == 0)
                atomicAdd(&s_sc[wm * 64 + mi * 16 + r * 8 + grp], v);
        }
    }
    __syncthreads();
    if (tid < 128) g_scores_part[npart][m0 + tid] = s_sc[tid];
}

// ---------------------------------------------------------------------------
// Kernel 3: fused softmax + context partial + last-block final reduce.
// ---------------------------------------------------------------------------
#define SPAN (SEQ / NSPLIT)   // 64

__global__ __launch_bounds__(256) void ctx_fused_kernel(
    float* __restrict__ w_out, float* __restrict__ ctx_out)
{
    __shared__ float e_sm[SEQ];      // 8KB
    __shared__ float sred[8];
    __shared__ int   is_last;
    const int b   = blockIdx.x;
    const int sp  = blockIdx.y;
    const int tid = threadIdx.x;

    // ---- softmax stats (sum the 8 N-split partials) ----
    float m = -1e30f;
    for (int i = tid; i < SEQ; i += 256) {
        float s = 0.f;
        #pragma unroll
        for (int q = 0; q < NPARTS; q++) s += g_scores_part[q][b * SEQ + i];
        e_sm[i] = s;
        m = fmaxf(m, s);
    }
    #pragma unroll
    for (int off = 16; off > 0; off >>= 1)
        m = fmaxf(m, __shfl_xor_sync(0xffffffffu, m, off));
    if ((tid & 31) == 0) sred[tid >> 5] = m;
    __syncthreads();
    if (tid == 0) {
        float mm = sred[0];
        #pragma unroll
        for (int i = 1; i < 8; i++) mm = fmaxf(mm, sred[i]);
        sred[0] = mm;
    }
    __syncthreads();
    const float bm = sred[0];
    __syncthreads();

    float sum = 0.f;
    for (int i = tid; i < SEQ; i += 256) {
        float e = __expf(e_sm[i] - bm);
        e_sm[i] = e;
        sum += e;
    }
    __syncthreads();
    #pragma unroll
    for (int off = 16; off > 0; off >>= 1)
        sum += __shfl_xor_sync(0xffffffffu, sum, off);
    if ((tid & 31) == 0) sred[tid >> 5] = sum;
    __syncthreads();
    if (tid == 0) {
        float s = 0.f;
        #pragma unroll
        for (int i = 0; i < 8; i++) s += sred[i];
        sred[0] = s;
    }
    __syncthreads();
    const float inv = 1.f / sred[0];

    const int s0 = sp * SPAN;

    if (w_out) {
        for (int i = s0 + tid; i < s0 + SPAN; i += 256)
            w_out[b * SEQ + i] = e_sm[i] * inv;
    }

    const uint2* vp = (const uint2*)(g_values_h + (size_t)b * SEQ * DIM);
    float4 acc = make_float4(0.f, 0.f, 0.f, 0.f);
    #pragma unroll 1
    for (int s = s0; s < s0 + SPAN; s += 4) {
        float w0 = e_sm[s]     * inv;
        float w1 = e_sm[s + 1] * inv;
        float w2 = e_sm[s + 2] * inv;
        float w3 = e_sm[s + 3] * inv;
        uint2 u0 = vp[(size_t)(s)     * 256 + tid];
        uint2 u1 = vp[(size_t)(s + 1) * 256 + tid];
        uint2 u2 = vp[(size_t)(s + 2) * 256 + tid];
        uint2 u3 = vp[(size_t)(s + 3) * 256 + tid];
        float2 a0 = __half22float2(*(const __half2*)&u0.x);
        float2 a1 = __half22float2(*(const __half2*)&u0.y);
        float2 b0 = __half22float2(*(const __half2*)&u1.x);
        float2 b1 = __half22float2(*(const __half2*)&u1.y);
        float2 c0 = __half22float2(*(const __half2*)&u2.x);
        float2 c1 = __half22float2(*(const __half2*)&u2.y);
        float2 d0 = __half22float2(*(const __half2*)&u3.x);
        float2 d1 = __half22float2(*(const __half2*)&u3.y);
        acc.x = fmaf(w0, a0.x, fmaf(w1, b0.x, fmaf(w2, c0.x, fmaf(w3, d0.x, acc.x))));
        acc.y = fmaf(w0, a0.y, fmaf(w1, b0.y, fmaf(w2, c0.y, fmaf(w3, d0.y, acc.y))));
        acc.z = fmaf(w0, a1.x, fmaf(w1, b1.x, fmaf(w2, c1.x, fmaf(w3, d1.x, acc.z))));
        acc.w = fmaf(w0, a1.y, fmaf(w1, b1.y, fmaf(w2, c1.y, fmaf(w3, d1.y, acc.w))));
    }
    ((float4*)&g_ctx_part[sp][b * DIM])[tid] = acc;

    if (!ctx_out) return;

    __threadfence();
    if (tid == 0)
        is_last = (atomicAdd(&g_ctr[b], 1) == NSPLIT - 1);
    __syncthreads();
    if (is_last) {
        float4 r = make_float4(0.f, 0.f, 0.f, 0.f);
        #pragma unroll
        for (int q = 0; q < NSPLIT; q++) {
            float4 v = ((const float4*)&g_ctx_part[q][b * DIM])[tid];
            r.x += v.x; r.y += v.y; r.z += v.z; r.w += v.w;
        }
        ((float4*)&ctx_out[b * DIM])[tid] = r;
    }
}

// ---------------------------------------------------------------------------
// Launch: inputs = query, values, W1, b1, W2, b2, V, bV
// ---------------------------------------------------------------------------
extern "C" void kernel_launch(void* const* d_in, const int* in_sizes, int n_in,
                              void* d_out, int out_size)
{
    const float* query  = (const float*)d_in[0];
    const float* values = (const float*)d_in[1];
    const float* W1     = (const float*)d_in[2];
    const float* b1     = (const float*)d_in[3];
    const float* W2     = (const float*)d_in[4];
    const float* b2     = (const float*)d_in[5];
    const float* V      = (const float*)d_in[6];
    // bV shifts every score equally -> softmax-invariant; unused.

    float* out = (float*)d_out;
    float* ctx_out = nullptr;
    float* w_out   = nullptr;
    if (out_size >= BATCH * DIM + BATCH * SEQ) {
        ctx_out = out;
        w_out   = out + BATCH * DIM;
    } else if (out_size == BATCH * SEQ) {
        w_out = out;
    } else {
        ctx_out = out;
    }

    static int smem_set = 0;
    if (!smem_set) {
        cudaFuncSetAttribute(score_kernel, cudaFuncAttributeMaxDynamicSharedMemorySize,
                             SMEM_SCORE_BYTES);
        smem_set = 1;
    }

    prep_kernel<<<PREP_GRID, 256>>>(query, values, W1, b1, W2, b2);
    score_kernel<<<(BATCH * SEQ) / 128 * NPARTS, 256, SMEM_SCORE_BYTES>>>(V);
    ctx_fused_kernel<<<dim3(BATCH, NSPLIT), 256>>>(w_out, ctx_out);
}

// round 16
// speedup vs baseline: 1.3490x; 1.0863x over previous
#include <cuda_runtime.h>
#include <cuda_fp16.h>
#include <stdint.h>
#include <math.h>

#define BATCH 32
#define SEQ   2048
#define DIM   1024
#define UNITS 1024

// ---------------------------------------------------------------------------
// Scratch (no device allocs allowed)
// ---------------------------------------------------------------------------
#define NSPLIT  32      // S-splits for context
#define NPARTS  8       // N-splits for score
__device__ __half g_values_h[BATCH * SEQ * DIM];   // fp16 copy of values (128MB)
__device__ __half g_W1T_h[UNITS * DIM];            // W1 transposed, fp16 [u][d]
__device__ float  g_qb[BATCH * UNITS];             // query@W2 + b2 + b1
__device__ float  g_scores_part[NPARTS][BATCH * SEQ];
__device__ float  g_ctx_part[NSPLIT][BATCH * DIM];
__device__ int    g_ctr[BATCH];                    // ctx completion counters

// ---------------------------------------------------------------------------
// PTX helpers
// ---------------------------------------------------------------------------
__device__ __forceinline__ uint32_t smem_u32(const void* p) {
    uint32_t a;
    asm("{ .reg .u64 t; cvta.to.shared.u64 t, %1; cvt.u32.u64 %0, t; }" : "=r"(a) : "l"(p));
    return a;
}
#define CP_ASYNC16(s, g) \
    asm volatile("cp.async.cg.shared.global [%0], [%1], 16;" :: "r"(s), "l"(g))
#define CP_COMMIT() asm volatile("cp.async.commit_group;" ::: "memory")
#define CP_WAIT0()  asm volatile("cp.async.wait_group 0;" ::: "memory")

// mma.sync m16n8k16 fp16 inputs, fp32 accum (baseline PTX, sm_80+)
__device__ __forceinline__ void mma_f16(float* d, const uint32_t* a, const uint32_t* b) {
    asm volatile(
        "mma.sync.aligned.m16n8k16.row.col.f32.f16.f16.f32 "
        "{%0,%1,%2,%3}, {%4,%5,%6,%7}, {%8,%9}, {%0,%1,%2,%3};"
        : "+f"(d[0]), "+f"(d[1]), "+f"(d[2]), "+f"(d[3])
        : "r"(a[0]), "r"(a[1]), "r"(a[2]), "r"(a[3]), "r"(b[0]), "r"(b[1]));
}

// ldmatrix x4 (baseline PTX, sm_75+)
__device__ __forceinline__ void ldsm_x4(uint32_t* r, uint32_t saddr) {
    asm volatile("ldmatrix.sync.aligned.m8n8.x4.shared.b16 {%0,%1,%2,%3}, [%4];"
        : "=r"(r[0]), "=r"(r[1]), "=r"(r[2]), "=r"(r[3]) : "r"(saddr));
}

// ---------------------------------------------------------------------------
// FMA-only tanh (no MUFU): abs err < ~5e-5
// ---------------------------------------------------------------------------
__device__ __forceinline__ float tanh_fast(float x) {
    float ax = fminf(fabsf(x), 10.0f);
    float t  = ax * 2.885390081777927f;
    float fn = t + 12582912.0f;
    int   n  = __float_as_int(fn) - __float_as_int(12582912.0f);
    float f  = t - (fn - 12582912.0f);
    float p  = 9.6181e-3f;
    p = fmaf(p, f, 5.5504e-2f);
    p = fmaf(p, f, 2.4022651e-1f);
    p = fmaf(p, f, 6.9314718e-1f);
    p = fmaf(p, f, 1.0f);
    float e = __int_as_float(__float_as_int(p) + (n << 23));
    float d = e + 1.0f;
    float r = __int_as_float(0x7EF311C3u - __float_as_int(d));
    r = r * fmaf(-d, r, 2.0f);
    r = r * fmaf(-d, r, 2.0f);
    float th = fmaf(-2.0f, r, 1.0f);
    return __int_as_float(__float_as_int(th) | (__float_as_int(x) & 0x80000000));
}

// ---------------------------------------------------------------------------
// Fused prep kernel: heterogeneous blocks, all jobs run concurrently.
//   qproj: 4 blocks per batch (256 u-cols each), W2 read coalesced, unroll 8.
//   convert: 32 floats/thread (8 independent LDG.128 -> 4 STG.128).
// ---------------------------------------------------------------------------
#define PREP_QPROJ_BLKS  (BATCH * 4)                            // 128
#define PREP_TRANS_BLKS  ((DIM / 32) * (UNITS / 32))            // 1024
#define PREP_CONV_BLKS   ((BATCH * SEQ * DIM) / (256 * 32))     // 8192
#define PREP_GRID        (PREP_QPROJ_BLKS + PREP_TRANS_BLKS + PREP_CONV_BLKS)

__global__ __launch_bounds__(256) void prep_kernel(
    const float* __restrict__ query, const float* __restrict__ values,
    const float* __restrict__ W1,   const float* __restrict__ b1,
    const float* __restrict__ W2,   const float* __restrict__ b2)
{
    const int tid = threadIdx.x;
    const int bid = blockIdx.x;

    if (bid < PREP_QPROJ_BLKS) {
        const int b  = bid >> 2;
        const int u  = (bid & 3) * 256 + tid;
        if (tid == 0 && (bid & 3) == 0) g_ctr[b] = 0;   // reset ctx counter
        __shared__ float qrow[DIM];
        for (int i = tid; i < DIM; i += 256)
            qrow[i] = query[b * DIM + i];
        __syncthreads();
        float acc = 0.f;
        #pragma unroll 8
        for (int d = 0; d < DIM; d++)
            acc = fmaf(qrow[d], W2[(size_t)d * UNITS + u], acc);
        g_qb[b * UNITS + u] = acc + b1[u] + b2[u];
    } else if (bid < PREP_QPROJ_BLKS + PREP_TRANS_BLKS) {
        __shared__ float t[32][33];
        const int tile = bid - PREP_QPROJ_BLKS;
        const int d0 = (tile & 31) * 32;
        const int u0 = (tile >> 5) * 32;
        const int tx = tid & 31;
        const int ty = tid >> 5;
        #pragma unroll
        for (int i = 0; i < 4; i++) {
            int r = ty + i * 8;
            t[r][tx] = W1[(size_t)(d0 + r) * UNITS + u0 + tx];
        }
        __syncthreads();
        #pragma unroll
        for (int i = 0; i < 4; i++) {
            int r = ty + i * 8;
            g_W1T_h[(size_t)(u0 + r) * DIM + d0 + tx] = __float2half_rn(t[tx][r]);
        }
    } else {
        // convert: 32 floats per thread, 8 independent LDG.128
        const size_t base = ((size_t)(bid - PREP_QPROJ_BLKS - PREP_TRANS_BLKS) * 256 + tid) * 8;
        const float4* in = (const float4*)values;
        float4 v[8];
        #pragma unroll
        for (int i = 0; i < 8; i++) v[i] = in[base + i];
        uint4 o[4];
        #pragma unroll
        for (int i = 0; i < 4; i++) {
            __half2 h0 = __floats2half2_rn(v[2*i].x,   v[2*i].y);
            __half2 h1 = __floats2half2_rn(v[2*i].z,   v[2*i].w);
            __half2 h2 = __floats2half2_rn(v[2*i+1].x, v[2*i+1].y);
            __half2 h3 = __floats2half2_rn(v[2*i+1].z, v[2*i+1].w);
            o[i].x = *(uint32_t*)&h0; o[i].y = *(uint32_t*)&h1;
            o[i].z = *(uint32_t*)&h2; o[i].w = *(uint32_t*)&h3;
        }
        uint4* op = (uint4*)g_values_h + base / 2;
        #pragma unroll
        for (int i = 0; i < 4; i++) op[i] = o[i];
    }
}

// ---------------------------------------------------------------------------
// Kernel 2: fused score GEMM via mma.sync fp16 (m16n8k16) + ldmatrix
// CTA tile 128(M) x 128(N) (one N-eighth), K chunks of 64 -> 16 chunks.
// Grid = 4096. 2 CTAs/SM (smem 74KB, regs <= 128). 2-stage cp.async.
// 256 threads = 8 warps (2M x 4N), warp tile 64x32.
// ---------------------------------------------------------------------------
#define KC        64
#define A_PITCH_H 72                   // 144 B rows: conflict-free LDSM + cp.async
#define B_PITCH_H 72
#define A_STAGE_H (128 * A_PITCH_H)    // 9216 halfs
#define B_STAGE_H (128 * B_PITCH_H)    // 9216 halfs
#define OFF_B_H   (2 * A_STAGE_H)      // 18432 halfs
#define SMEM_HALFS (OFF_B_H + 2 * B_STAGE_H)         // 36864 halfs
#define OFF_SC_BYTES (SMEM_HALFS * 2)                // 73728
#define SMEM_SCORE_BYTES (OFF_SC_BYTES + 128 * 4)    // 74240

__device__ __forceinline__ void load_chunk(uint32_t sb, int stage, int m0, int n0,
                                           int c, int tid)
{
    const int k0 = c * KC;
    const uint32_t a_s = sb + stage * A_STAGE_H * 2;
    const uint32_t b_s = sb + (OFF_B_H + stage * B_STAGE_H) * 2;
    #pragma unroll
    for (int t = 0; t < 4; t++) {
        int idx = tid + t * 256;
        int r = idx >> 3, cc = idx & 7;
        CP_ASYNC16(a_s + r * 144 + cc * 16,
                   g_values_h + (size_t)(m0 + r) * DIM + k0 + cc * 8);
    }
    #pragma unroll
    for (int t = 0; t < 4; t++) {
        int idx = tid + t * 256;
        int r = idx >> 3, cc = idx & 7;
        CP_ASYNC16(b_s + r * 144 + cc * 16,
                   g_W1T_h + (size_t)(n0 + r) * DIM + k0 + cc * 8);
    }
}

__global__ __launch_bounds__(256, 2) void score_kernel(const float* __restrict__ V)
{
    extern __shared__ __align__(16) char smraw[];
    float* s_sc = (float*)(smraw + OFF_SC_BYTES);
    const uint32_t sb = smem_u32(smraw);

    const int tid  = threadIdx.x;
    const int warp = tid >> 5;
    const int lane = tid & 31;
    const int wm   = warp >> 2;          // 0..1 (M)
    const int wn   = warp & 3;           // 0..3 (N)
    const int grp  = lane >> 2;          // 0..7
    const int ctg  = lane & 3;           // 0..3
    const int npart = blockIdx.x & 7;                // 0..7
    const int m0    = (blockIdx.x >> 3) * 128;
    const int nbase = npart * 128;
    const int b     = m0 >> 11;

    const int lrow = ((lane >> 3) & 1) * 8 + (lane & 7);   // 0..15
    const int lkoc = ((lane >> 4) & 1) * 8;                // 0 or 8

    if (tid < 128) s_sc[tid] = 0.f;

    float acc[4][4][4];
    #pragma unroll
    for (int mi = 0; mi < 4; mi++)
        #pragma unroll
        for (int ni = 0; ni < 4; ni++)
            #pragma unroll
            for (int r = 0; r < 4; r++)
                acc[mi][ni][r] = 0.f;

    load_chunk(sb, 0, m0, nbase, 0, tid); CP_COMMIT();

    for (int c = 0; c < 16; c++) {
        const int stage = c & 1;
        CP_WAIT0();
        __syncthreads();
        if (c + 1 < 16) {
            load_chunk(sb, (c + 1) & 1, m0, nbase, c + 1, tid);
            CP_COMMIT();
        }

        const uint32_t a_base = sb + stage * A_STAGE_H * 2
                              + ((wm * 64 + lrow) * A_PITCH_H + lkoc) * 2;
        const uint32_t b_base = sb + (OFF_B_H + stage * B_STAGE_H) * 2
                              + ((wn * 32 + lrow) * B_PITCH_H + lkoc) * 2;

        #pragma unroll
        for (int k16 = 0; k16 < KC / 16; k16++) {
            const int kb = k16 * 16;
            uint32_t afr[4][4], bfr[4][2];
            #pragma unroll
            for (int mi = 0; mi < 4; mi++)
                ldsm_x4(afr[mi], a_base + (mi * 16 * A_PITCH_H + kb) * 2);
            #pragma unroll
            for (int pr = 0; pr < 2; pr++) {
                uint32_t tmp[4];
                ldsm_x4(tmp, b_base + (pr * 16 * B_PITCH_H + kb) * 2);
                bfr[2 * pr][0]     = tmp[0];
                bfr[2 * pr + 1][0] = tmp[1];
                bfr[2 * pr][1]     = tmp[2];
                bfr[2 * pr + 1][1] = tmp[3];
            }
            #pragma unroll
            for (int mi = 0; mi < 4; mi++)
                #pragma unroll
                for (int ni = 0; ni < 4; ni++)
                    mma_f16(acc[mi][ni], afr[mi], bfr[ni]);
        }
        __syncthreads();
    }

    // epilogue: tanh(acc + qb) * V for this CTA's N-eighth
    float p[4][2];
    #pragma unroll
    for (int i = 0; i < 4; i++) { p[i][0] = 0.f; p[i][1] = 0.f; }
    #pragma unroll
    for (int ni = 0; ni < 4; ni++) {
        const int nloc = nbase + wn * 32 + ni * 8 + ctg * 2;
        const float2 q2 = *(const float2*)&g_qb[b * UNITS + nloc];
        const float2 v2 = *(const float2*)&V[nloc];
        #pragma unroll
        for (int mi = 0; mi < 4; mi++) {
            p[mi][0] = fmaf(tanh_fast(acc[mi][ni][0] + q2.x), v2.x, p[mi][0]);
            p[mi][0] = fmaf(tanh_fast(acc[mi][ni][1] + q2.y), v2.y, p[mi][0]);
            p[mi][1] = fmaf(tanh_fast(acc[mi][ni][2] + q2.x), v2.x, p[mi][1]);
            p[mi][1] = fmaf(tanh_fast(acc[mi][ni][3] + q2.y), v2.y, p[mi][1]);
        }
    }

    #pragma unroll
    for (int mi = 0; mi < 4; mi++) {
        #pragma unroll
        for (int r = 0; r < 2; r++) {
            float v = p[mi][r];
            v += __shfl_xor_sync(0xffffffffu, v, 1);
            v += __shfl_xor_sync(0xffffffffu, v, 2);
            if (ctg == 0)
                atomicAdd(&s_sc[wm * 64 + mi * 16 + r * 8 + grp], v);
        }
    }
    __syncthreads();
    if (tid < 128) g_scores_part[npart][m0 + tid] = s_sc[tid];
}

// ---------------------------------------------------------------------------
// Kernel 3: fused softmax + context partial + last-block final reduce.
// ---------------------------------------------------------------------------
#define SPAN (SEQ / NSPLIT)   // 64

__global__ __launch_bounds__(256) void ctx_fused_kernel(
    float* __restrict__ w_out, float* __restrict__ ctx_out)
{
    __shared__ float e_sm[SEQ];      // 8KB
    __shared__ float sred[8];
    __shared__ int   is_last;
    const int b   = blockIdx.x;
    const int sp  = blockIdx.y;
    const int tid = threadIdx.x;

    // ---- softmax stats (sum the 8 N-split partials) ----
    float m = -1e30f;
    for (int i = tid; i < SEQ; i += 256) {
        float s = 0.f;
        #pragma unroll
        for (int q = 0; q < NPARTS; q++) s += g_scores_part[q][b * SEQ + i];
        e_sm[i] = s;
        m = fmaxf(m, s);
    }
    #pragma unroll
    for (int off = 16; off > 0; off >>= 1)
        m = fmaxf(m, __shfl_xor_sync(0xffffffffu, m, off));
    if ((tid & 31) == 0) sred[tid >> 5] = m;
    __syncthreads();
    if (tid == 0) {
        float mm = sred[0];
        #pragma unroll
        for (int i = 1; i < 8; i++) mm = fmaxf(mm, sred[i]);
        sred[0] = mm;
    }
    __syncthreads();
    const float bm = sred[0];
    __syncthreads();

    float sum = 0.f;
    for (int i = tid; i < SEQ; i += 256) {
        float e = __expf(e_sm[i] - bm);
        e_sm[i] = e;
        sum += e;
    }
    __syncthreads();
    #pragma unroll
    for (int off = 16; off > 0; off >>= 1)
        sum += __shfl_xor_sync(0xffffffffu, sum, off);
    if ((tid & 31) == 0) sred[tid >> 5] = sum;
    __syncthreads();
    if (tid == 0) {
        float s = 0.f;
        #pragma unroll
        for (int i = 0; i < 8; i++) s += sred[i];
        sred[0] = s;
    }
    __syncthreads();
    const float inv = 1.f / sred[0];

    const int s0 = sp * SPAN;

    if (w_out) {
        for (int i = s0 + tid; i < s0 + SPAN; i += 256)
            w_out[b * SEQ + i] = e_sm[i] * inv;
    }

    const uint2* vp = (const uint2*)(g_values_h + (size_t)b * SEQ * DIM);
    float4 acc = make_float4(0.f, 0.f, 0.f, 0.f);
    #pragma unroll 1
    for (int s = s0; s < s0 + SPAN; s += 4) {
        float w0 = e_sm[s]     * inv;
        float w1 = e_sm[s + 1] * inv;
        float w2 = e_sm[s + 2] * inv;
        float w3 = e_sm[s + 3] * inv;
        uint2 u0 = vp[(size_t)(s)     * 256 + tid];
        uint2 u1 = vp[(size_t)(s + 1) * 256 + tid];
        uint2 u2 = vp[(size_t)(s + 2) * 256 + tid];
        uint2 u3 = vp[(size_t)(s + 3) * 256 + tid];
        float2 a0 = __half22float2(*(const __half2*)&u0.x);
        float2 a1 = __half22float2(*(const __half2*)&u0.y);
        float2 b0 = __half22float2(*(const __half2*)&u1.x);
        float2 b1 = __half22float2(*(const __half2*)&u1.y);
        float2 c0 = __half22float2(*(const __half2*)&u2.x);
        float2 c1 = __half22float2(*(const __half2*)&u2.y);
        float2 d0 = __half22float2(*(const __half2*)&u3.x);
        float2 d1 = __half22float2(*(const __half2*)&u3.y);
        acc.x = fmaf(w0, a0.x, fmaf(w1, b0.x, fmaf(w2, c0.x, fmaf(w3, d0.x, acc.x))));
        acc.y = fmaf(w0, a0.y, fmaf(w1, b0.y, fmaf(w2, c0.y, fmaf(w3, d0.y, acc.y))));
        acc.z = fmaf(w0, a1.x, fmaf(w1, b1.x, fmaf(w2, c1.x, fmaf(w3, d1.x, acc.z))));
        acc.w = fmaf(w0, a1.y, fmaf(w1, b1.y, fmaf(w2, c1.y, fmaf(w3, d1.y, acc.w))));
    }
    ((float4*)&g_ctx_part[sp][b * DIM])[tid] = acc;

    if (!ctx_out) return;

    __threadfence();
    if (tid == 0)
        is_last = (atomicAdd(&g_ctr[b], 1) == NSPLIT - 1);
    __syncthreads();
    if (is_last) {
        float4 r = make_float4(0.f, 0.f, 0.f, 0.f);
        #pragma unroll
        for (int q = 0; q < NSPLIT; q++) {
            float4 v = ((const float4*)&g_ctx_part[q][b * DIM])[tid];
            r.x += v.x; r.y += v.y; r.z += v.z; r.w += v.w;
        }
        ((float4*)&ctx_out[b * DIM])[tid] = r;
    }
}

// ---------------------------------------------------------------------------
// Launch: inputs = query, values, W1, b1, W2, b2, V, bV
// ---------------------------------------------------------------------------
extern "C" void kernel_launch(void* const* d_in, const int* in_sizes, int n_in,
                              void* d_out, int out_size)
{
    const float* query  = (const float*)d_in[0];
    const float* values = (const float*)d_in[1];
    const float* W1     = (const float*)d_in[2];
    const float* b1     = (const float*)d_in[3];
    const float* W2     = (const float*)d_in[4];
    const float* b2     = (const float*)d_in[5];
    const float* V      = (const float*)d_in[6];
    // bV shifts every score equally -> softmax-invariant; unused.

    float* out = (float*)d_out;
    float* ctx_out = nullptr;
    float* w_out   = nullptr;
    if (out_size >= BATCH * DIM + BATCH * SEQ) {
        ctx_out = out;
        w_out   = out + BATCH * DIM;
    } else if (out_size == BATCH * SEQ) {
        w_out = out;
    } else {
        ctx_out = out;
    }

    static int smem_set = 0;
    if (!smem_set) {
        cudaFuncSetAttribute(score_kernel, cudaFuncAttributeMaxDynamicSharedMemorySize,
                             SMEM_SCORE_BYTES);
        smem_set = 1;
    }

    prep_kernel<<<PREP_GRID, 256>>>(query, values, W1, b1, W2, b2);
    score_kernel<<<(BATCH * SEQ) / 128 * NPARTS, 256, SMEM_SCORE_BYTES>>>(V);
    ctx_fused_kernel<<<dim3(BATCH, NSPLIT), 256>>>(w_out, ctx_out);
}

// round 17
// speedup vs baseline: 1.3516x; 1.0019x over previous
#include <cuda_runtime.h>
#include <cuda_fp16.h>
#include <stdint.h>
#include <math.h>

#define BATCH 32
#define SEQ   2048
#define DIM   1024
#define UNITS 1024

// ---------------------------------------------------------------------------
// Scratch (no device allocs allowed)
// ---------------------------------------------------------------------------
#define NSPLIT  32      // S-splits for context
#define NPARTS  8       // N-splits for score
__device__ __half g_values_h[BATCH * SEQ * DIM];   // fp16 copy of values (128MB)
__device__ __half g_W1T_h[UNITS * DIM];            // W1 transposed, fp16 [u][d]
__device__ float  g_qb[BATCH * UNITS];             // query@W2 + b2 + b1
__device__ float  g_scores_part[NPARTS][BATCH * SEQ];
__device__ float  g_ctx_part[NSPLIT][BATCH * DIM];
__device__ int    g_ctr[BATCH];                    // ctx completion counters

// ---------------------------------------------------------------------------
// PTX helpers
// ---------------------------------------------------------------------------
__device__ __forceinline__ uint32_t smem_u32(const void* p) {
    uint32_t a;
    asm("{ .reg .u64 t; cvta.to.shared.u64 t, %1; cvt.u32.u64 %0, t; }" : "=r"(a) : "l"(p));
    return a;
}
#define CP_ASYNC16(s, g) \
    asm volatile("cp.async.cg.shared.global [%0], [%1], 16;" :: "r"(s), "l"(g))
#define CP_COMMIT() asm volatile("cp.async.commit_group;" ::: "memory")
#define CP_WAIT0()  asm volatile("cp.async.wait_group 0;" ::: "memory")

// mma.sync m16n8k16 fp16 inputs, fp32 accum (baseline PTX, sm_80+)
__device__ __forceinline__ void mma_f16(float* d, const uint32_t* a, const uint32_t* b) {
    asm volatile(
        "mma.sync.aligned.m16n8k16.row.col.f32.f16.f16.f32 "
        "{%0,%1,%2,%3}, {%4,%5,%6,%7}, {%8,%9}, {%0,%1,%2,%3};"
        : "+f"(d[0]), "+f"(d[1]), "+f"(d[2]), "+f"(d[3])
        : "r"(a[0]), "r"(a[1]), "r"(a[2]), "r"(a[3]), "r"(b[0]), "r"(b[1]));
}

// ldmatrix x4 (baseline PTX, sm_75+)
__device__ __forceinline__ void ldsm_x4(uint32_t* r, uint32_t saddr) {
    asm volatile("ldmatrix.sync.aligned.m8n8.x4.shared.b16 {%0,%1,%2,%3}, [%4];"
        : "=r"(r[0]), "=r"(r[1]), "=r"(r[2]), "=r"(r[3]) : "r"(saddr));
}

// ---------------------------------------------------------------------------
// FMA-only tanh (no MUFU): abs err < ~5e-5
// ---------------------------------------------------------------------------
__device__ __forceinline__ float tanh_fast(float x) {
    float ax = fminf(fabsf(x), 10.0f);
    float t  = ax * 2.885390081777927f;
    float fn = t + 12582912.0f;
    int   n  = __float_as_int(fn) - __float_as_int(12582912.0f);
    float f  = t - (fn - 12582912.0f);
    float p  = 9.6181e-3f;
    p = fmaf(p, f, 5.5504e-2f);
    p = fmaf(p, f, 2.4022651e-1f);
    p = fmaf(p, f, 6.9314718e-1f);
    p = fmaf(p, f, 1.0f);
    float e = __int_as_float(__float_as_int(p) + (n << 23));
    float d = e + 1.0f;
    float r = __int_as_float(0x7EF311C3u - __float_as_int(d));
    r = r * fmaf(-d, r, 2.0f);
    r = r * fmaf(-d, r, 2.0f);
    float th = fmaf(-2.0f, r, 1.0f);
    return __int_as_float(__float_as_int(th) | (__float_as_int(x) & 0x80000000));
}

// ---------------------------------------------------------------------------
// Fused prep kernel: heterogeneous blocks, all jobs run concurrently.
//   qproj: 4 blocks per batch, W2 read coalesced.
//   convert: 32 floats/thread, streaming cache hints (data used once here).
// ---------------------------------------------------------------------------
#define PREP_QPROJ_BLKS  (BATCH * 4)                            // 128
#define PREP_TRANS_BLKS  ((DIM / 32) * (UNITS / 32))            // 1024
#define PREP_CONV_BLKS   ((BATCH * SEQ * DIM) / (256 * 32))     // 8192
#define PREP_GRID        (PREP_QPROJ_BLKS + PREP_TRANS_BLKS + PREP_CONV_BLKS)

__global__ __launch_bounds__(256) void prep_kernel(
    const float* __restrict__ query, const float* __restrict__ values,
    const float* __restrict__ W1,   const float* __restrict__ b1,
    const float* __restrict__ W2,   const float* __restrict__ b2)
{
    const int tid = threadIdx.x;
    const int bid = blockIdx.x;

    if (bid < PREP_QPROJ_BLKS) {
        const int b  = bid >> 2;
        const int u  = (bid & 3) * 256 + tid;
        if (tid == 0 && (bid & 3) == 0) g_ctr[b] = 0;   // reset ctx counter
        __shared__ float qrow[DIM];
        for (int i = tid; i < DIM; i += 256)
            qrow[i] = query[b * DIM + i];
        __syncthreads();
        float acc = 0.f;
        #pragma unroll 8
        for (int d = 0; d < DIM; d++)
            acc = fmaf(qrow[d], W2[(size_t)d * UNITS + u], acc);
        g_qb[b * UNITS + u] = acc + b1[u] + b2[u];
    } else if (bid < PREP_QPROJ_BLKS + PREP_TRANS_BLKS) {
        __shared__ float t[32][33];
        const int tile = bid - PREP_QPROJ_BLKS;
        const int d0 = (tile & 31) * 32;
        const int u0 = (tile >> 5) * 32;
        const int tx = tid & 31;
        const int ty = tid >> 5;
        #pragma unroll
        for (int i = 0; i < 4; i++) {
            int r = ty + i * 8;
            t[r][tx] = W1[(size_t)(d0 + r) * UNITS + u0 + tx];
        }
        __syncthreads();
        #pragma unroll
        for (int i = 0; i < 4; i++) {
            int r = ty + i * 8;
            g_W1T_h[(size_t)(u0 + r) * DIM + d0 + tx] = __float2half_rn(t[tx][r]);
        }
    } else {
        // convert: 32 floats per thread, 8 independent streaming LDG.128
        const size_t base = ((size_t)(bid - PREP_QPROJ_BLKS - PREP_TRANS_BLKS) * 256 + tid) * 8;
        const float4* in = (const float4*)values;
        float4 v[8];
        #pragma unroll
        for (int i = 0; i < 8; i++) v[i] = __ldcs(&in[base + i]);
        uint4 o[4];
        #pragma unroll
        for (int i = 0; i < 4; i++) {
            __half2 h0 = __floats2half2_rn(v[2*i].x,   v[2*i].y);
            __half2 h1 = __floats2half2_rn(v[2*i].z,   v[2*i].w);
            __half2 h2 = __floats2half2_rn(v[2*i+1].x, v[2*i+1].y);
            __half2 h3 = __floats2half2_rn(v[2*i+1].z, v[2*i+1].w);
            o[i].x = *(uint32_t*)&h0; o[i].y = *(uint32_t*)&h1;
            o[i].z = *(uint32_t*)&h2; o[i].w = *(uint32_t*)&h3;
        }
        uint4* op = (uint4*)g_values_h + base / 2;
        #pragma unroll
        for (int i = 0; i < 4; i++) __stcs(&op[i], o[i]);
    }
}

// ---------------------------------------------------------------------------
// Kernel 2: fused score GEMM via mma.sync fp16 (m16n8k16) + ldmatrix
// CTA tile 128(M) x 128(N) (one N-eighth), K chunks of 64 -> 16 chunks.
// Grid = 4096. 2 CTAs/SM (smem 74KB). 128 threads = 4 warps (2M x 2N),
// warp tile 64x64 (mi=4, ni=8) -> LDSM redundancy A 2x, B 2x (was 4x/2x).
// 2-stage cp.async pipeline.
// ---------------------------------------------------------------------------
#define KC        64
#define A_PITCH_H 72                   // 144 B rows: conflict-free LDSM + cp.async
#define B_PITCH_H 72
#define A_STAGE_H (128 * A_PITCH_H)    // 9216 halfs
#define B_STAGE_H (128 * B_PITCH_H)    // 9216 halfs
#define OFF_B_H   (2 * A_STAGE_H)      // 18432 halfs
#define SMEM_HALFS (OFF_B_H + 2 * B_STAGE_H)         // 36864 halfs
#define OFF_SC_BYTES (SMEM_HALFS * 2)                // 73728
#define SMEM_SCORE_BYTES (OFF_SC_BYTES + 128 * 4)    // 74240

__device__ __forceinline__ void load_chunk(uint32_t sb, int stage, int m0, int n0,
                                           int c, int tid)
{
    const int k0 = c * KC;
    const uint32_t a_s = sb + stage * A_STAGE_H * 2;
    const uint32_t b_s = sb + (OFF_B_H + stage * B_STAGE_H) * 2;
    // A: values_h tile 128 x 64 halfs (1024 16B chunks / 128 thr = 8)
    #pragma unroll
    for (int t = 0; t < 8; t++) {
        int idx = tid + t * 128;
        int r = idx >> 3, cc = idx & 7;
        CP_ASYNC16(a_s + r * 144 + cc * 16,
                   g_values_h + (size_t)(m0 + r) * DIM + k0 + cc * 8);
    }
    // B: W1T_h tile 128 x 64 halfs
    #pragma unroll
    for (int t = 0; t < 8; t++) {
        int idx = tid + t * 128;
        int r = idx >> 3, cc = idx & 7;
        CP_ASYNC16(b_s + r * 144 + cc * 16,
                   g_W1T_h + (size_t)(n0 + r) * DIM + k0 + cc * 8);
    }
}

__global__ __launch_bounds__(128, 2) void score_kernel(const float* __restrict__ V)
{
    extern __shared__ __align__(16) char smraw[];
    float* s_sc = (float*)(smraw + OFF_SC_BYTES);
    const uint32_t sb = smem_u32(smraw);

    const int tid  = threadIdx.x;
    const int warp = tid >> 5;           // 0..3
    const int lane = tid & 31;
    const int wm   = warp >> 1;          // 0..1 (M)
    const int wn   = warp & 1;           // 0..1 (N)
    const int grp  = lane >> 2;          // 0..7
    const int ctg  = lane & 3;           // 0..3
    const int npart = blockIdx.x & 7;                // 0..7
    const int m0    = (blockIdx.x >> 3) * 128;
    const int nbase = npart * 128;
    const int b     = m0 >> 11;

    const int lrow = ((lane >> 3) & 1) * 8 + (lane & 7);   // 0..15
    const int lkoc = ((lane >> 4) & 1) * 8;                // 0 or 8

    if (tid < 128) s_sc[tid] = 0.f;

    float acc[4][8][4];
    #pragma unroll
    for (int mi = 0; mi < 4; mi++)
        #pragma unroll
        for (int ni = 0; ni < 8; ni++)
            #pragma unroll
            for (int r = 0; r < 4; r++)
                acc[mi][ni][r] = 0.f;

    load_chunk(sb, 0, m0, nbase, 0, tid); CP_COMMIT();

    for (int c = 0; c < 16; c++) {
        const int stage = c & 1;
        CP_WAIT0();
        __syncthreads();
        if (c + 1 < 16) {
            load_chunk(sb, (c + 1) & 1, m0, nbase, c + 1, tid);
            CP_COMMIT();
        }

        const uint32_t a_base = sb + stage * A_STAGE_H * 2
                              + ((wm * 64 + lrow) * A_PITCH_H + lkoc) * 2;
        const uint32_t b_base = sb + (OFF_B_H + stage * B_STAGE_H) * 2
                              + ((wn * 64 + lrow) * B_PITCH_H + lkoc) * 2;

        #pragma unroll
        for (int k16 = 0; k16 < KC / 16; k16++) {
            const int kb = k16 * 16;
            uint32_t afr[4][4], bfr[8][2];
            #pragma unroll
            for (int mi = 0; mi < 4; mi++)
                ldsm_x4(afr[mi], a_base + (mi * 16 * A_PITCH_H + kb) * 2);
            #pragma unroll
            for (int pr = 0; pr < 4; pr++) {
                uint32_t tmp[4];
                ldsm_x4(tmp, b_base + (pr * 16 * B_PITCH_H + kb) * 2);
                bfr[2 * pr][0]     = tmp[0];
                bfr[2 * pr + 1][0] = tmp[1];
                bfr[2 * pr][1]     = tmp[2];
                bfr[2 * pr + 1][1] = tmp[3];
            }
            #pragma unroll
            for (int mi = 0; mi < 4; mi++)
                #pragma unroll
                for (int ni = 0; ni < 8; ni++)
                    mma_f16(acc[mi][ni], afr[mi], bfr[ni]);
        }
        __syncthreads();
    }

    // epilogue: tanh(acc + qb) * V for this CTA's N-eighth
    float p[4][2];
    #pragma unroll
    for (int i = 0; i < 4; i++) { p[i][0] = 0.f; p[i][1] = 0.f; }
    #pragma unroll
    for (int ni = 0; ni < 8; ni++) {
        const int nloc = nbase + wn * 64 + ni * 8 + ctg * 2;
        const float2 q2 = *(const float2*)&g_qb[b * UNITS + nloc];
        const float2 v2 = *(const float2*)&V[nloc];
        #pragma unroll
        for (int mi = 0; mi < 4; mi++) {
            p[mi][0] = fmaf(tanh_fast(acc[mi][ni][0] + q2.x), v2.x, p[mi][0]);
            p[mi][0] = fmaf(tanh_fast(acc[mi][ni][1] + q2.y), v2.y, p[mi][0]);
            p[mi][1] = fmaf(tanh_fast(acc[mi][ni][2] + q2.x), v2.x, p[mi][1]);
            p[mi][1] = fmaf(tanh_fast(acc[mi][ni][3] + q2.y), v2.y, p[mi][1]);
        }
    }

    // reduce over quad lanes (ctg), then across the 2 n-warps via smem atomics
    #pragma unroll
    for (int mi = 0; mi < 4; mi++) {
        #pragma unroll
        for (int r = 0; r < 2; r++) {
            float v = p[mi][r];
            v += __shfl_xor_sync(0xffffffffu, v, 1);
            v += __shfl_xor_sync(0xffffffffu, v, 2);
            if (ctg == 0)
                atomicAdd(&s_sc[wm * 64 + mi * 16 + r * 8 + grp], v);
        }
    }
    __syncthreads();
    if (tid < 128) g_scores_part[npart][m0 + tid] = s_sc[tid];
}

// ---------------------------------------------------------------------------
// Kernel 3: fused softmax + context partial + last-block final reduce.
// ---------------------------------------------------------------------------
#define SPAN (SEQ / NSPLIT)   // 64

__global__ __launch_bounds__(256) void ctx_fused_kernel(
    float* __restrict__ w_out, float* __restrict__ ctx_out)
{
    __shared__ float e_sm[SEQ];      // 8KB
    __shared__ float sred[8];
    __shared__ int   is_last;
    const int b   = blockIdx.x;
    const int sp  = blockIdx.y;
    const int tid = threadIdx.x;

    // ---- softmax stats (sum the 8 N-split partials) ----
    float m = -1e30f;
    for (int i = tid; i < SEQ; i += 256) {
        float s = 0.f;
        #pragma unroll
        for (int q = 0; q < NPARTS; q++) s += g_scores_part[q][b * SEQ + i];
        e_sm[i] = s;
        m = fmaxf(m, s);
    }
    #pragma unroll
    for (int off = 16; off > 0; off >>= 1)
        m = fmaxf(m, __shfl_xor_sync(0xffffffffu, m, off));
    if ((tid & 31) == 0) sred[tid >> 5] = m;
    __syncthreads();
    if (tid == 0) {
        float mm = sred[0];
        #pragma unroll
        for (int i = 1; i < 8; i++) mm = fmaxf(mm, sred[i]);
        sred[0] = mm;
    }
    __syncthreads();
    const float bm = sred[0];
    __syncthreads();

    float sum = 0.f;
    for (int i = tid; i < SEQ; i += 256) {
        float e = __expf(e_sm[i] - bm);
        e_sm[i] = e;
        sum += e;
    }
    __syncthreads();
    #pragma unroll
    for (int off = 16; off > 0; off >>= 1)
        sum += __shfl_xor_sync(0xffffffffu, sum, off);
    if ((tid & 31) == 0) sred[tid >> 5] = sum;
    __syncthreads();
    if (tid == 0) {
        float s = 0.f;
        #pragma unroll
        for (int i = 0; i < 8; i++) s += sred[i];
        sred[0] = s;
    }
    __syncthreads();
    const float inv = 1.f / sred[0];

    const int s0 = sp * SPAN;

    if (w_out) {
        for (int i = s0 + tid; i < s0 + SPAN; i += 256)
            w_out[b * SEQ + i] = e_sm[i] * inv;
    }

    const uint2* vp = (const uint2*)(g_values_h + (size_t)b * SEQ * DIM);
    float4 acc = make_float4(0.f, 0.f, 0.f, 0.f);
    #pragma unroll 1
    for (int s = s0; s < s0 + SPAN; s += 4) {
        float w0 = e_sm[s]     * inv;
        float w1 = e_sm[s + 1] * inv;
        float w2 = e_sm[s + 2] * inv;
        float w3 = e_sm[s + 3] * inv;
        uint2 u0 = vp[(size_t)(s)     * 256 + tid];
        uint2 u1 = vp[(size_t)(s + 1) * 256 + tid];
        uint2 u2 = vp[(size_t)(s + 2) * 256 + tid];
        uint2 u3 = vp[(size_t)(s + 3) * 256 + tid];
        float2 a0 = __half22float2(*(const __half2*)&u0.x);
        float2 a1 = __half22float2(*(const __half2*)&u0.y);
        float2 b0 = __half22float2(*(const __half2*)&u1.x);
        float2 b1 = __half22float2(*(const __half2*)&u1.y);
        float2 c0 = __half22float2(*(const __half2*)&u2.x);
        float2 c1 = __half22float2(*(const __half2*)&u2.y);
        float2 d0 = __half22float2(*(const __half2*)&u3.x);
        float2 d1 = __half22float2(*(const __half2*)&u3.y);
        acc.x = fmaf(w0, a0.x, fmaf(w1, b0.x, fmaf(w2, c0.x, fmaf(w3, d0.x, acc.x))));
        acc.y = fmaf(w0, a0.y, fmaf(w1, b0.y, fmaf(w2, c0.y, fmaf(w3, d0.y, acc.y))));
        acc.z = fmaf(w0, a1.x, fmaf(w1, b1.x, fmaf(w2, c1.x, fmaf(w3, d1.x, acc.z))));
        acc.w = fmaf(w0, a1.y, fmaf(w1, b1.y, fmaf(w2, c1.y, fmaf(w3, d1.y, acc.w))));
    }
    ((float4*)&g_ctx_part[sp][b * DIM])[tid] = acc;

    if (!ctx_out) return;

    __threadfence();
    if (tid == 0)
        is_last = (atomicAdd(&g_ctr[b], 1) == NSPLIT - 1);
    __syncthreads();
    if (is_last) {
        float4 r = make_float4(0.f, 0.f, 0.f, 0.f);
        #pragma unroll
        for (int q = 0; q < NSPLIT; q++) {
            float4 v = ((const float4*)&g_ctx_part[q][b * DIM])[tid];
            r.x += v.x; r.y += v.y; r.z += v.z; r.w += v.w;
        }
        ((float4*)&ctx_out[b * DIM])[tid] = r;
    }
}

// ---------------------------------------------------------------------------
// Launch: inputs = query, values, W1, b1, W2, b2, V, bV
// ---------------------------------------------------------------------------
extern "C" void kernel_launch(void* const* d_in, const int* in_sizes, int n_in,
                              void* d_out, int out_size)
{
    const float* query  = (const float*)d_in[0];
    const float* values = (const float*)d_in[1];
    const float* W1     = (const float*)d_in[2];
    const float* b1     = (const float*)d_in[3];
    const float* W2     = (const float*)d_in[4];
    const float* b2     = (const float*)d_in[5];
    const float* V      = (const float*)d_in[6];
    // bV shifts every score equally -> softmax-invariant; unused.

    float* out = (float*)d_out;
    float* ctx_out = nullptr;
    float* w_out   = nullptr;
    if (out_size >= BATCH * DIM + BATCH * SEQ) {
        ctx_out = out;
        w_out   = out + BATCH * DIM;
    } else if (out_size == BATCH * SEQ) {
        w_out = out;
    } else {
        ctx_out = out;
    }

    static int smem_set = 0;
    if (!smem_set) {
        cudaFuncSetAttribute(score_kernel, cudaFuncAttributeMaxDynamicSharedMemorySize,
                             SMEM_SCORE_BYTES);
        smem_set = 1;
    }

    prep_kernel<<<PREP_GRID, 256>>>(query, values, W1, b1, W2, b2);
    score_kernel<<<(BATCH * SEQ) / 128 * NPARTS, 128, SMEM_SCORE_BYTES>>>(V);
    ctx_fused_kernel<<<dim3(BATCH, NSPLIT), 256>>>(w_out, ctx_out);
}